// round 6
// baseline (speedup 1.0000x reference)
#include <cuda_runtime.h>
#include <cuda_fp16.h>
#include <cstdint>

// AWQ INT4 dequant GEMM: C[64, 28672] = A[64, 8192] @ dequant(qweight) + bias
// Harness dtype map has no fp16: A/scales/bias arrive as float32, out is float32.
// Pre-pass converts A to fp16 statics (exact); scales/bias converted inline.
//
// R5 layout: NTILE=64, 128 threads (4 warps: 2M x 2N), grid=448 -> single wave
// at occ>=4 (n_conc = 148*4 = 592 >= 448). 4-stage cp.async pipeline.

#define MDIM 64
#define KDIM 8192
#define NDIM 28672
#define NGROUPS (KDIM / 128)   // 64
#define NTILE 64
#define KB 64
#define NCHUNK (KDIM / KB)     // 128
#define THREADS 128
#define STAGES 4

__device__ half g_A[MDIM * KDIM];          // 1 MB

__device__ __forceinline__ uint32_t smem_u32(const void* p) {
    return (uint32_t)__cvta_generic_to_shared(p);
}

__global__ void convert_A_kernel(const float* __restrict__ A)
{
    const int stride = gridDim.x * blockDim.x;
    for (int j = blockIdx.x * blockDim.x + threadIdx.x; j < MDIM * KDIM / 2; j += stride) {
        float2 v = reinterpret_cast<const float2*>(A)[j];
        reinterpret_cast<half2*>(g_A)[j] = __floats2half2_rn(v.x, v.y);
    }
}

__global__ __launch_bounds__(THREADS, 5)
void awq_gemm_kernel(const int*   __restrict__ qw,
                     const float* __restrict__ scales,
                     const float* __restrict__ bias,
                     float*       __restrict__ out)
{
    // 4-stage staging. A_sm rows padded to 72 halves for conflict-free ldmatrix.
    __shared__ half A_sm[STAGES][64][72];   // 36864 B
    __shared__ int  q_sm[STAGES][8][64];    //  8192 B

    const int tid  = threadIdx.x;
    const int lane = tid & 31;
    const int wid  = tid >> 5;
    const int wn   = wid & 1;          // warp col 0..1 (32 N each)
    const int wm   = wid >> 1;         // warp row 0..1 (32 M each)
    const int gidq = lane >> 2;        // 0..7  (mma group id)
    const int tj   = lane & 3;         // 0..3  (thread-in-group)

    const int n0 = blockIdx.x * NTILE;

    // Staging indices
    const int arow = tid >> 1;             // A row 0..63
    const int acol = (tid & 1) * 32;       // base half-offset (two 64B halves of row)
    const int kqr  = tid >> 4;             // q word-row 0..7
    const int nq4  = (tid & 15) * 4;       // q col (x4 words = 16B)

    float acc[2][4][4];
    #pragma unroll
    for (int i = 0; i < 2; i++)
        #pragma unroll
        for (int j = 0; j < 4; j++)
            #pragma unroll
            for (int k = 0; k < 4; k++) acc[i][j][k] = 0.f;

    half2 s2[4];
    const half2 C1032 = __half2half2(__ushort_as_half((unsigned short)0x6408)); // 1032.0 exact

    auto issue_chunk = [&](int c) {
        const int b  = c & (STAGES - 1);
        const int k0 = c * KB;
        #pragma unroll
        for (int j = 0; j < 4; ++j) {
            const int koff = acol + j * 8;
            const half* src = g_A + arow * KDIM + k0 + koff;
            uint32_t dst = smem_u32(&A_sm[b][arow][koff]);
            asm volatile("cp.async.cg.shared.global [%0], [%1], 16;\n"
                         :: "r"(dst), "l"(src));
        }
        {
            const int* src = qw + (size_t)(k0 / 8 + kqr) * NDIM + n0 + nq4;
            uint32_t dst = smem_u32(&q_sm[b][kqr][nq4]);
            asm volatile("cp.async.cg.shared.global [%0], [%1], 16;\n"
                         :: "r"(dst), "l"(src));
        }
        asm volatile("cp.async.commit_group;\n" ::: "memory");
    };

    issue_chunk(0);
    issue_chunk(1);
    issue_chunk(2);

    // scale column per nb: n0 + wn*32 + nb*8 + gidq
    const int scol = n0 + wn * 32 + gidq;

    for (int g = 0; g < NGROUPS; ++g) {
        // Per-group scales (f32 -> fp16, exact same rounding as reference)
        #pragma unroll
        for (int nb = 0; nb < 4; ++nb) {
            float sf = __ldg(scales + (size_t)g * NDIM + scol + nb * 8);
            s2[nb] = __half2half2(__float2half_rn(sf));
        }

        #pragma unroll
        for (int h = 0; h < 2; ++h) {
            const int c = g * 2 + h;
            if (c + STAGES - 1 < NCHUNK) {
                issue_chunk(c + STAGES - 1);
                asm volatile("cp.async.wait_group %0;\n" :: "n"(STAGES - 1) : "memory");
            } else {
                asm volatile("cp.async.wait_group 0;\n" ::: "memory");
            }
            __syncthreads();

            const int b = c & (STAGES - 1);

            #pragma unroll
            for (int s = 0; s < 4; ++s) {
                uint32_t a[2][4];
                #pragma unroll
                for (int mf = 0; mf < 2; ++mf) {
                    const int row = wm * 32 + mf * 16 + (lane & 15);
                    const int col = s * 16 + ((lane >> 4) << 3);
                    uint32_t addr = smem_u32(&A_sm[b][row][col]);
                    asm volatile("ldmatrix.sync.aligned.m8n8.x4.shared.b16 {%0,%1,%2,%3}, [%4];\n"
                                 : "=r"(a[mf][0]), "=r"(a[mf][1]),
                                   "=r"(a[mf][2]), "=r"(a[mf][3])
                                 : "r"(addr));
                }
                #pragma unroll
                for (int nb = 0; nb < 4; ++nb) {
                    const int ncol = wn * 32 + nb * 8 + gidq;
                    // byte tj of word 2s holds k-rows {2tj,2tj+1}; word 2s+1 -> {8+2tj,9+2tj}
                    uint32_t w0 = (uint32_t)q_sm[b][2 * s][ncol];
                    uint32_t w1 = (uint32_t)q_sm[b][2 * s + 1][ncol];
                    uint32_t q0 = w0 >> (tj * 8);
                    uint32_t q1 = w1 >> (tj * 8);
                    // {1024+nib_lo, 1024+nib_hi} fp16x2 (exact), isolated masks
                    uint32_t v0 = (q0 & 0x0000000Fu) | ((q0 & 0x000000F0u) << 12) | 0x64006400u;
                    uint32_t v1 = (q1 & 0x0000000Fu) | ((q1 & 0x000000F0u) << 12) | 0x64006400u;
                    half2 h0 = __hmul2(__hsub2(*reinterpret_cast<half2*>(&v0), C1032), s2[nb]);
                    half2 h1 = __hmul2(__hsub2(*reinterpret_cast<half2*>(&v1), C1032), s2[nb]);
                    uint32_t b0 = reinterpret_cast<uint32_t&>(h0);
                    uint32_t b1 = reinterpret_cast<uint32_t&>(h1);
                    #pragma unroll
                    for (int mf = 0; mf < 2; ++mf) {
                        asm volatile(
                            "mma.sync.aligned.m16n8k16.row.col.f32.f16.f16.f32 "
                            "{%0,%1,%2,%3}, {%4,%5,%6,%7}, {%8,%9}, {%0,%1,%2,%3};\n"
                            : "+f"(acc[mf][nb][0]), "+f"(acc[mf][nb][1]),
                              "+f"(acc[mf][nb][2]), "+f"(acc[mf][nb][3])
                            : "r"(a[mf][0]), "r"(a[mf][1]), "r"(a[mf][2]), "r"(a[mf][3]),
                              "r"(b0), "r"(b1));
                    }
                }
            }
            __syncthreads();
        }
    }

    // Epilogue: fp32 acc -> fp16 round, + fp16(bias) (reference numerics),
    // widen to f32 for the output buffer.
    #pragma unroll
    for (int mf = 0; mf < 2; ++mf) {
        #pragma unroll
        for (int nb = 0; nb < 4; ++nb) {
            const int col = n0 + wn * 32 + nb * 8 + 2 * tj;
            const float2 bf = *reinterpret_cast<const float2*>(bias + col);
            const half2 bb = __floats2half2_rn(bf.x, bf.y);
            const int row0 = wm * 32 + mf * 16 + gidq;
            half2 o0 = __hadd2(__floats2half2_rn(acc[mf][nb][0], acc[mf][nb][1]), bb);
            half2 o1 = __hadd2(__floats2half2_rn(acc[mf][nb][2], acc[mf][nb][3]), bb);
            float2 f0 = make_float2(__low2float(o0), __high2float(o0));
            float2 f1 = make_float2(__low2float(o1), __high2float(o1));
            *reinterpret_cast<float2*>(out + (size_t)row0 * NDIM + col)       = f0;
            *reinterpret_cast<float2*>(out + (size_t)(row0 + 8) * NDIM + col) = f1;
        }
    }
}

extern "C" void kernel_launch(void* const* d_in, const int* in_sizes, int n_in,
                              void* d_out, int out_size) {
    // Bind inputs by element count (all four counts are distinct).
    const float* A      = nullptr;
    const int*   qwt    = nullptr;
    const float* scales = nullptr;
    const float* bias   = nullptr;
    for (int i = 0; i < n_in; ++i) {
        switch (in_sizes[i]) {
            case MDIM * KDIM:        A      = (const float*)d_in[i]; break; // 524288
            case (KDIM / 8) * NDIM:  qwt    = (const int*)d_in[i];   break; // 29360128
            case NGROUPS * NDIM:     scales = (const float*)d_in[i]; break; // 1835008
            case NDIM:               bias   = (const float*)d_in[i]; break; // 28672
            default: break;
        }
    }
    float* out = (float*)d_out;

    convert_A_kernel<<<128, 256>>>(A);
    awq_gemm_kernel<<<NDIM / NTILE, THREADS>>>(qwt, scales, bias, out);  // 448 CTAs
}

// round 7
// speedup vs baseline: 1.1516x; 1.1516x over previous
#include <cuda_runtime.h>
#include <cuda_fp16.h>
#include <cstdint>

// AWQ INT4 dequant GEMM: C[64, 28672] = A[64, 8192] @ dequant(qweight) + bias
// Harness dtype map has no fp16: A/scales/bias arrive as f32, out is f32.
//
// R6: split-K=2 (896 CTAs, all resident, 24 warps/SM) + B-reuse over all 64 M
// rows (each dequantized B fragment feeds 4 MMAs). 3-stage cp.async pipeline.
// Partials accumulated via f32 red.global (2 adds/elem -> deterministic),
// finalize kernel applies reference fp16 rounding + fp16 bias.

#define MDIM 64
#define KDIM 8192
#define NDIM 28672
#define NGROUPS (KDIM / 128)   // 64
#define NTILE 64
#define KB 64
#define NCHUNK (KDIM / KB)     // 128
#define CHALF (NCHUNK / 2)     // 64 chunks per K-split
#define GHALF (NGROUPS / 2)    // 32 groups per K-split
#define THREADS 128
#define STAGES 3

__device__ half g_A[MDIM * KDIM];          // 1 MB

__device__ __forceinline__ uint32_t smem_u32(const void* p) {
    return (uint32_t)__cvta_generic_to_shared(p);
}

__global__ void convert_A_kernel(const float* __restrict__ A)
{
    const int stride = gridDim.x * blockDim.x;
    for (int j = blockIdx.x * blockDim.x + threadIdx.x; j < MDIM * KDIM / 2; j += stride) {
        float2 v = reinterpret_cast<const float2*>(A)[j];
        reinterpret_cast<half2*>(g_A)[j] = __floats2half2_rn(v.x, v.y);
    }
}

__global__ __launch_bounds__(THREADS, 6)
void awq_gemm_kernel(const int*   __restrict__ qw,
                     const float* __restrict__ scales,
                     float*       __restrict__ out)
{
    __shared__ half A_sm[STAGES][64][72];   // 27648 B (72 pad: conflict-free ldmatrix)
    __shared__ int  q_sm[STAGES][8][64];    //  6144 B

    const int tid  = threadIdx.x;
    const int lane = tid & 31;
    const int wn   = tid >> 5;         // warp owns 16 N cols: [wn*16, wn*16+16)
    const int gidq = lane >> 2;        // 0..7  (mma group id)
    const int tj   = lane & 3;         // 0..3  (thread-in-group)

    const int n0 = blockIdx.x * NTILE;
    const int kh = blockIdx.y;         // K split half
    const int cbase = kh * CHALF;

    // Staging indices
    const int arow = tid >> 1;             // A row 0..63
    const int acol = (tid & 1) * 32;       // half-offset within row
    const int kqr  = tid >> 4;             // q word-row 0..7
    const int nq4  = (tid & 15) * 4;       // q col (x4 words = 16B)

    float acc[4][2][4];                    // [mf][nb][frag]
    #pragma unroll
    for (int i = 0; i < 4; i++)
        #pragma unroll
        for (int j = 0; j < 2; j++)
            #pragma unroll
            for (int k = 0; k < 4; k++) acc[i][j][k] = 0.f;

    half2 s2[2];
    const half2 C1032 = __half2half2(__ushort_as_half((unsigned short)0x6408)); // 1032.0 exact

    auto issue_chunk = [&](int c) {
        const int b  = c % STAGES;
        const int k0 = c * KB;
        #pragma unroll
        for (int j = 0; j < 4; ++j) {
            const int koff = acol + j * 8;
            const half* src = g_A + arow * KDIM + k0 + koff;
            uint32_t dst = smem_u32(&A_sm[b][arow][koff]);
            asm volatile("cp.async.cg.shared.global [%0], [%1], 16;\n"
                         :: "r"(dst), "l"(src));
        }
        {
            const int* src = qw + (size_t)(k0 / 8 + kqr) * NDIM + n0 + nq4;
            uint32_t dst = smem_u32(&q_sm[b][kqr][nq4]);
            asm volatile("cp.async.cg.shared.global [%0], [%1], 16;\n"
                         :: "r"(dst), "l"(src));
        }
        asm volatile("cp.async.commit_group;\n" ::: "memory");
    };

    issue_chunk(cbase + 0);
    issue_chunk(cbase + 1);

    const int scol = n0 + wn * 16 + gidq;

    for (int g = 0; g < GHALF; ++g) {
        const int gg = kh * GHALF + g;
        #pragma unroll
        for (int nb = 0; nb < 2; ++nb) {
            float sf = __ldg(scales + (size_t)gg * NDIM + scol + nb * 8);
            s2[nb] = __half2half2(__float2half_rn(sf));
        }

        #pragma unroll
        for (int h = 0; h < 2; ++h) {
            const int c = cbase + g * 2 + h;
            if (c + 2 < cbase + CHALF) {
                issue_chunk(c + 2);
                asm volatile("cp.async.wait_group 2;\n" ::: "memory");
            } else {
                asm volatile("cp.async.wait_group 0;\n" ::: "memory");
            }
            __syncthreads();

            const int b = c % STAGES;

            #pragma unroll
            for (int s = 0; s < 4; ++s) {
                // A fragments: all 64 M rows (4 x m16 frags), identical across warps
                uint32_t a[4][4];
                #pragma unroll
                for (int mf = 0; mf < 4; ++mf) {
                    const int row = mf * 16 + (lane & 15);
                    const int col = s * 16 + ((lane >> 4) << 3);
                    uint32_t addr = smem_u32(&A_sm[b][row][col]);
                    asm volatile("ldmatrix.sync.aligned.m8n8.x4.shared.b16 {%0,%1,%2,%3}, [%4];\n"
                                 : "=r"(a[mf][0]), "=r"(a[mf][1]),
                                   "=r"(a[mf][2]), "=r"(a[mf][3])
                                 : "r"(addr));
                }
                #pragma unroll
                for (int nb = 0; nb < 2; ++nb) {
                    const int ncol = wn * 16 + nb * 8 + gidq;
                    // byte tj of word 2s holds k-rows {2tj,2tj+1}; word 2s+1 -> {8+2tj,9+2tj}
                    uint32_t w0 = (uint32_t)q_sm[b][2 * s][ncol];
                    uint32_t w1 = (uint32_t)q_sm[b][2 * s + 1][ncol];
                    uint32_t q0 = w0 >> (tj * 8);
                    uint32_t q1 = w1 >> (tj * 8);
                    uint32_t v0 = (q0 & 0x0000000Fu) | ((q0 & 0x000000F0u) << 12) | 0x64006400u;
                    uint32_t v1 = (q1 & 0x0000000Fu) | ((q1 & 0x000000F0u) << 12) | 0x64006400u;
                    half2 h0 = __hmul2(__hsub2(*reinterpret_cast<half2*>(&v0), C1032), s2[nb]);
                    half2 h1 = __hmul2(__hsub2(*reinterpret_cast<half2*>(&v1), C1032), s2[nb]);
                    uint32_t b0 = reinterpret_cast<uint32_t&>(h0);
                    uint32_t b1 = reinterpret_cast<uint32_t&>(h1);
                    #pragma unroll
                    for (int mf = 0; mf < 4; ++mf) {
                        asm volatile(
                            "mma.sync.aligned.m16n8k16.row.col.f32.f16.f16.f32 "
                            "{%0,%1,%2,%3}, {%4,%5,%6,%7}, {%8,%9}, {%0,%1,%2,%3};\n"
                            : "+f"(acc[mf][nb][0]), "+f"(acc[mf][nb][1]),
                              "+f"(acc[mf][nb][2]), "+f"(acc[mf][nb][3])
                            : "r"(a[mf][0]), "r"(a[mf][1]), "r"(a[mf][2]), "r"(a[mf][3]),
                              "r"(b0), "r"(b1));
                    }
                }
            }
            __syncthreads();
        }
    }

    // Epilogue: accumulate f32 partials into out (exactly 2 adds per element
    // across kh=0,1 -> commutative -> deterministic bits).
    #pragma unroll
    for (int mf = 0; mf < 4; ++mf) {
        #pragma unroll
        for (int nb = 0; nb < 2; ++nb) {
            const int col  = n0 + wn * 16 + nb * 8 + 2 * tj;
            const int row0 = mf * 16 + gidq;
            atomicAdd(out + (size_t)row0 * NDIM + col,           acc[mf][nb][0]);
            atomicAdd(out + (size_t)row0 * NDIM + col + 1,       acc[mf][nb][1]);
            atomicAdd(out + (size_t)(row0 + 8) * NDIM + col,     acc[mf][nb][2]);
            atomicAdd(out + (size_t)(row0 + 8) * NDIM + col + 1, acc[mf][nb][3]);
        }
    }
}

// Reference numerics: fp16(round(acc_f32)) + fp16(bias), widened to f32.
__global__ void finalize_kernel(float* __restrict__ out,
                                const float* __restrict__ bias)
{
    const int stride = gridDim.x * blockDim.x;
    const int total2 = MDIM * NDIM / 2;
    for (int j = blockIdx.x * blockDim.x + threadIdx.x; j < total2; j += stride) {
        const int col = (j * 2) % NDIM;
        float2 v = reinterpret_cast<float2*>(out)[j];
        const float2 bf = *reinterpret_cast<const float2*>(bias + col);
        half2 hb = __floats2half2_rn(bf.x, bf.y);
        half2 hv = __floats2half2_rn(v.x, v.y);
        half2 o  = __hadd2(hv, hb);
        reinterpret_cast<float2*>(out)[j] =
            make_float2(__low2float(o), __high2float(o));
    }
}

extern "C" void kernel_launch(void* const* d_in, const int* in_sizes, int n_in,
                              void* d_out, int out_size) {
    // Bind inputs by element count (all four counts are distinct).
    const float* A      = nullptr;
    const int*   qwt    = nullptr;
    const float* scales = nullptr;
    const float* bias   = nullptr;
    for (int i = 0; i < n_in; ++i) {
        switch (in_sizes[i]) {
            case MDIM * KDIM:        A      = (const float*)d_in[i]; break; // 524288
            case (KDIM / 8) * NDIM:  qwt    = (const int*)d_in[i];   break; // 29360128
            case NGROUPS * NDIM:     scales = (const float*)d_in[i]; break; // 1835008
            case NDIM:               bias   = (const float*)d_in[i]; break; // 28672
            default: break;
        }
    }
    float* out = (float*)d_out;

    convert_A_kernel<<<128, 256>>>(A);
    cudaMemsetAsync(out, 0, (size_t)MDIM * NDIM * sizeof(float));
    dim3 grid(NDIM / NTILE, 2);   // 448 x 2 = 896 CTAs, all resident
    awq_gemm_kernel<<<grid, THREADS>>>(qwt, scales, out);
    finalize_kernel<<<1792, 256>>>(out, bias);
}

// round 10
// speedup vs baseline: 1.5767x; 1.3691x over previous
#include <cuda_runtime.h>
#include <cuda_fp16.h>
#include <cstdint>

// AWQ INT4 dequant GEMM: C[64,28672] = A[64,8192] @ deq(qweight) + bias
// f32 in (harness has no fp16), f32 out. mma.sync m16n8k16 (tcgen05 is
// rejected by this harness's compute_103 PTX target).
//
// R9: no __syncthreads in mainloop. A staged via cp.async.bulk (1D bulk TMA,
// one elected issue per chunk) into a 4-stage ring gated by full/free
// mbarriers; prepass retiles A to contiguous 8KB/chunk with ldmatrix bank
// XOR pre-applied. q goes global->registers per warp (coalesced LDG.32) and
// is redistributed with shuffles. Split-K=2, grid 896, 128 thr, occ 6.

#define MDIM 64
#define KDIM 8192
#define NDIM 28672
#define NGROUPS 64
#define NTILE 64
#define KB 64
#define CHALF 64              // chunks per CTA (split-K = 2)
#define THREADS 128
#define STAGES 4
#define A_STAGE_BYTES 8192    // 64 rows x 128 B
#define DSMEM (STAGES * A_STAGE_BYTES + 1024)

__device__ half g_A2[128 * 4096];   // 1 MB: [chunk][row][swizzled 16B-chunks]

__device__ __forceinline__ uint32_t smem_u32(const void* p) {
    return (uint32_t)__cvta_generic_to_shared(p);
}
__device__ __forceinline__ void mbar_init(uint32_t a, uint32_t cnt) {
    asm volatile("mbarrier.init.shared.b64 [%0], %1;" :: "r"(a), "r"(cnt) : "memory");
}
__device__ __forceinline__ void mbar_wait(uint32_t a, uint32_t parity) {
    asm volatile(
        "{\n\t.reg .pred P;\n\t"
        "W_%=:\n\t"
        "mbarrier.try_wait.parity.acquire.cta.shared::cta.b64 P, [%0], %1, 0x989680;\n\t"
        "@P bra.uni D_%=;\n\t"
        "bra.uni W_%=;\n\t"
        "D_%=:\n\t}"
        :: "r"(a), "r"(parity) : "memory");
}
__device__ __forceinline__ void mbar_arrive(uint32_t a) {
    asm volatile("mbarrier.arrive.shared.b64 _, [%0];" :: "r"(a) : "memory");
}
__device__ __forceinline__ void bulk_ld(uint32_t dst, const void* src, uint32_t mbar) {
    asm volatile("mbarrier.arrive.expect_tx.shared.b64 _, [%0], %1;"
                 :: "r"(mbar), "r"((uint32_t)A_STAGE_BYTES) : "memory");
    asm volatile("cp.async.bulk.shared::cluster.global.mbarrier::complete_tx::bytes "
                 "[%0], [%1], %2, [%3];"
                 :: "r"(dst), "l"(src), "r"((uint32_t)A_STAGE_BYTES), "r"(mbar) : "memory");
}

// Prepass: f32 A -> fp16, retiled [chunk][row][16B-chunk j], j XOR (row&7).
__global__ void convert_A(const float* __restrict__ A)
{
    int id = blockIdx.x * blockDim.x + threadIdx.x;
    if (id >= 128 * 64 * 8) return;
    int cg = id >> 9;
    int r  = (id >> 3) & 63;
    int j  = id & 7;
    const float4 f0 = *reinterpret_cast<const float4*>(A + (size_t)r * KDIM + cg * 64 + j * 8);
    const float4 f1 = *reinterpret_cast<const float4*>(A + (size_t)r * KDIM + cg * 64 + j * 8 + 4);
    half2 h[4] = { __floats2half2_rn(f0.x, f0.y), __floats2half2_rn(f0.z, f0.w),
                   __floats2half2_rn(f1.x, f1.y), __floats2half2_rn(f1.z, f1.w) };
    *reinterpret_cast<uint4*>(g_A2 + (size_t)cg * 4096 + r * 64 + ((j ^ (r & 7)) * 8)) =
        *reinterpret_cast<uint4*>(h);
}

__global__ __launch_bounds__(THREADS, 6)
void awq_gemm_kernel(const int*   __restrict__ qw,
                     const float* __restrict__ scales,
                     float*       __restrict__ out)
{
    extern __shared__ char dsm_raw[];
    __shared__ __align__(8) uint64_t m_full[STAGES];
    __shared__ __align__(8) uint64_t m_free[STAGES];

    uint32_t raw = smem_u32(dsm_raw);
    const uint32_t A_smem = (raw + 1023u) & ~1023u;

    const int tid  = threadIdx.x;
    const int lane = tid & 31;
    const int wid  = tid >> 5;          // warp owns cols [wid*16, wid*16+16)
    const int gidq = lane >> 2;         // 0..7
    const int tj   = lane & 3;          // 0..3
    const int n0   = blockIdx.x * NTILE;
    const int kh   = blockIdx.y;        // K half
    const int cb   = kh * CHALF;        // global chunk base

    if (tid == 0) {
        #pragma unroll
        for (int s = 0; s < STAGES; ++s) {
            mbar_init(smem_u32(&m_full[s]), 1);
            mbar_init(smem_u32(&m_free[s]), 4);
        }
    }
    __syncthreads();

    // Prologue: issue A chunks 0..2
    if (tid == 0) {
        #pragma unroll
        for (int p = 0; p < 3; ++p)
            bulk_ld(A_smem + p * A_STAGE_BYTES, g_A2 + (size_t)(cb + p) * 4096,
                    smem_u32(&m_full[p]));
    }

    // q: per-warp direct LDG. Round r loads word-rows {2r, 2r+1}:
    // lanes 0-15 row 2r, lanes 16-31 row 2r+1; col = lane&15 within warp's 16.
    const int kwofs = lane >> 4;
    const int qcol  = n0 + wid * 16 + (lane & 15);
    uint32_t qc[4], qn[4];
    #pragma unroll
    for (int r = 0; r < 4; ++r)
        qc[r] = __ldg((const uint32_t*)qw + (size_t)(cb * 8 + 2 * r + kwofs) * NDIM + qcol);

    // scales: cols wid*16 + gidq (+8)
    const int scol = n0 + wid * 16 + gidq;
    float sf0 = __ldg(scales + (size_t)(kh * 32) * NDIM + scol);
    float sf1 = __ldg(scales + (size_t)(kh * 32) * NDIM + scol + 8);

    float acc[4][2][4];
    #pragma unroll
    for (int i = 0; i < 4; i++)
        #pragma unroll
        for (int j = 0; j < 2; j++)
            #pragma unroll
            for (int k = 0; k < 4; k++) acc[i][j][k] = 0.f;

    half2 s2[2];
    const half2 C1032 = __half2half2(__ushort_as_half((unsigned short)0x6408)); // 1032.0

    for (int c = 0; c < CHALF; ++c) {
        // Producer: issue chunk c+3 (wait stage free for c+3 >= 4)
        if (tid == 0 && c + 3 < CHALF) {
            const int cc = c + 3, st = cc & 3;
            if (cc >= 4) mbar_wait(smem_u32(&m_free[st]), ((cc >> 2) - 1) & 1);
            bulk_ld(A_smem + st * A_STAGE_BYTES, g_A2 + (size_t)(cb + cc) * 4096,
                    smem_u32(&m_full[st]));
        }
        // q prefetch next chunk
        if (c + 1 < CHALF) {
            #pragma unroll
            for (int r = 0; r < 4; ++r)
                qn[r] = __ldg((const uint32_t*)qw +
                              (size_t)((cb + c + 1) * 8 + 2 * r + kwofs) * NDIM + qcol);
        }
        // group scales (128 K = 2 chunks)
        if ((c & 1) == 0) {
            s2[0] = __half2half2(__float2half_rn(sf0));
            s2[1] = __half2half2(__float2half_rn(sf1));
            const int gn = kh * 32 + (c >> 1) + 1;
            if (gn < (kh + 1) * 32) {
                sf0 = __ldg(scales + (size_t)gn * NDIM + scol);
                sf1 = __ldg(scales + (size_t)gn * NDIM + scol + 8);
            }
        }

        // A stage ready?
        const int st = c & 3;
        mbar_wait(smem_u32(&m_full[st]), (c >> 2) & 1);
        const uint32_t abase = A_smem + st * A_STAGE_BYTES;

        #pragma unroll
        for (int s = 0; s < 4; ++s) {
            uint32_t a[4][4];
            #pragma unroll
            for (int mf = 0; mf < 4; ++mf) {
                const int row = mf * 16 + (lane & 15);
                const int j   = (2 * s + (lane >> 4)) ^ (row & 7);
                uint32_t addr = abase + row * 128 + j * 16;
                asm volatile("ldmatrix.sync.aligned.m8n8.x4.shared.b16 {%0,%1,%2,%3}, [%4];\n"
                             : "=r"(a[mf][0]), "=r"(a[mf][1]),
                               "=r"(a[mf][2]), "=r"(a[mf][3])
                             : "r"(addr));
            }
            #pragma unroll
            for (int nb = 0; nb < 2; ++nb) {
                const int src = nb * 8 + gidq;
                uint32_t w0 = __shfl_sync(0xffffffffu, qc[s], src);       // word-row 2s
                uint32_t w1 = __shfl_sync(0xffffffffu, qc[s], src + 16);  // word-row 2s+1
                uint32_t q0 = w0 >> (tj * 8);
                uint32_t q1 = w1 >> (tj * 8);
                uint32_t v0 = (q0 & 0x0000000Fu) | ((q0 & 0x000000F0u) << 12) | 0x64006400u;
                uint32_t v1 = (q1 & 0x0000000Fu) | ((q1 & 0x000000F0u) << 12) | 0x64006400u;
                half2 h0 = __hmul2(__hsub2(reinterpret_cast<half2&>(v0), C1032), s2[nb]);
                half2 h1 = __hmul2(__hsub2(reinterpret_cast<half2&>(v1), C1032), s2[nb]);
                uint32_t b0 = reinterpret_cast<uint32_t&>(h0);
                uint32_t b1 = reinterpret_cast<uint32_t&>(h1);
                #pragma unroll
                for (int mf = 0; mf < 4; ++mf) {
                    asm volatile(
                        "mma.sync.aligned.m16n8k16.row.col.f32.f16.f16.f32 "
                        "{%0,%1,%2,%3}, {%4,%5,%6,%7}, {%8,%9}, {%0,%1,%2,%3};\n"
                        : "+f"(acc[mf][nb][0]), "+f"(acc[mf][nb][1]),
                          "+f"(acc[mf][nb][2]), "+f"(acc[mf][nb][3])
                        : "r"(a[mf][0]), "r"(a[mf][1]), "r"(a[mf][2]), "r"(a[mf][3]),
                          "r"(b0), "r"(b1));
                }
            }
        }
        if (lane == 0) mbar_arrive(smem_u32(&m_free[st]));
        #pragma unroll
        for (int r = 0; r < 4; ++r) qc[r] = qn[r];
    }

    // Epilogue: f32 partial accumulate (2 adds/elem across kh -> deterministic)
    #pragma unroll
    for (int mf = 0; mf < 4; ++mf) {
        #pragma unroll
        for (int nb = 0; nb < 2; ++nb) {
            const int col  = n0 + wid * 16 + nb * 8 + 2 * tj;
            const int row0 = mf * 16 + gidq;
            atomicAdd(out + (size_t)row0 * NDIM + col,           acc[mf][nb][0]);
            atomicAdd(out + (size_t)row0 * NDIM + col + 1,       acc[mf][nb][1]);
            atomicAdd(out + (size_t)(row0 + 8) * NDIM + col,     acc[mf][nb][2]);
            atomicAdd(out + (size_t)(row0 + 8) * NDIM + col + 1, acc[mf][nb][3]);
        }
    }
}

// Reference numerics: f32( fp16(acc) + fp16(bias) )
__global__ void finalize_kernel(float* __restrict__ out,
                                const float* __restrict__ bias)
{
    const int stride = gridDim.x * blockDim.x;
    const int total2 = MDIM * NDIM / 2;
    for (int j = blockIdx.x * blockDim.x + threadIdx.x; j < total2; j += stride) {
        const int col = (j * 2) % NDIM;
        float2 v = reinterpret_cast<float2*>(out)[j];
        const float2 bf = *reinterpret_cast<const float2*>(bias + col);
        half2 hb = __floats2half2_rn(bf.x, bf.y);
        half2 hv = __floats2half2_rn(v.x, v.y);
        half2 o  = __hadd2(hv, hb);
        reinterpret_cast<float2*>(out)[j] = make_float2(__low2float(o), __high2float(o));
    }
}

extern "C" void kernel_launch(void* const* d_in, const int* in_sizes, int n_in,
                              void* d_out, int out_size) {
    const float* A      = nullptr;
    const int*   qwt    = nullptr;
    const float* scales = nullptr;
    const float* bias   = nullptr;
    for (int i = 0; i < n_in; ++i) {
        switch (in_sizes[i]) {
            case MDIM * KDIM:        A      = (const float*)d_in[i]; break;
            case (KDIM / 8) * NDIM:  qwt    = (const int*)d_in[i];   break;
            case NGROUPS * NDIM:     scales = (const float*)d_in[i]; break;
            case NDIM:               bias   = (const float*)d_in[i]; break;
            default: break;
        }
    }
    float* out = (float*)d_out;

    cudaFuncSetAttribute(awq_gemm_kernel, cudaFuncAttributeMaxDynamicSharedMemorySize, DSMEM);
    convert_A<<<256, 256>>>(A);
    cudaMemsetAsync(out, 0, (size_t)MDIM * NDIM * sizeof(float));
    dim3 grid(NDIM / NTILE, 2);    // 448 x 2 = 896 CTAs
    awq_gemm_kernel<<<grid, THREADS, DSMEM>>>(qwt, scales, out);
    finalize_kernel<<<1792, 256>>>(out, bias);
}

// round 12
// speedup vs baseline: 1.5975x; 1.0132x over previous
#include <cuda_runtime.h>
#include <cuda_fp16.h>
#include <cstdint>

// AWQ INT4 dequant GEMM: C[64,28672] = A[64,8192] @ deq(qweight) + bias
// f32 in (harness has no fp16), f32 out. mma.sync m16n8k16 (tcgen05 rejected
// at compute_103 PTX target).
//
// R11: intra-CTA split-K (2 K-groups x 4 N-warps, per-group 4-stage
// cp.async.bulk A ring). Epilogue reduction now uses a DEDICATED static
// __shared__ buffer (two passes, 8 KB) instead of aliasing the TMA-written
// ring smem -- R10's cross-proxy WAW hazard (async-proxy bulk writes vs
// generic-proxy scratch stores to the same addresses) is gone.

#define MDIM 64
#define KDIM 8192
#define NDIM 28672
#define NGROUPS 64
#define NTILE 64
#define CHALF 64              // chunks per K-group
#define THREADS 256
#define STAGES 4
#define A_STAGE_BYTES 8192    // 64 rows x 128 B
#define DSMEM (2 * STAGES * A_STAGE_BYTES + 1024)

__device__ half g_A2[128 * 4096];   // 1 MB: [chunk][row][swizzled 16B-chunks]

__device__ __forceinline__ uint32_t smem_u32(const void* p) {
    return (uint32_t)__cvta_generic_to_shared(p);
}
__device__ __forceinline__ void mbar_init(uint32_t a, uint32_t cnt) {
    asm volatile("mbarrier.init.shared.b64 [%0], %1;" :: "r"(a), "r"(cnt) : "memory");
}
__device__ __forceinline__ void mbar_wait(uint32_t a, uint32_t parity) {
    asm volatile(
        "{\n\t.reg .pred P;\n\t"
        "W_%=:\n\t"
        "mbarrier.try_wait.parity.acquire.cta.shared::cta.b64 P, [%0], %1, 0x989680;\n\t"
        "@P bra.uni D_%=;\n\t"
        "bra.uni W_%=;\n\t"
        "D_%=:\n\t}"
        :: "r"(a), "r"(parity) : "memory");
}
__device__ __forceinline__ void mbar_arrive(uint32_t a) {
    asm volatile("mbarrier.arrive.shared.b64 _, [%0];" :: "r"(a) : "memory");
}
__device__ __forceinline__ void bulk_ld(uint32_t dst, const void* src, uint32_t mbar) {
    asm volatile("mbarrier.arrive.expect_tx.shared.b64 _, [%0], %1;"
                 :: "r"(mbar), "r"((uint32_t)A_STAGE_BYTES) : "memory");
    asm volatile("cp.async.bulk.shared::cluster.global.mbarrier::complete_tx::bytes "
                 "[%0], [%1], %2, [%3];"
                 :: "r"(dst), "l"(src), "r"((uint32_t)A_STAGE_BYTES), "r"(mbar) : "memory");
}

// Prepass: f32 A -> fp16, retiled [chunk][row][16B-chunk j], j XOR (row&7).
__global__ void convert_A(const float* __restrict__ A)
{
    int id = blockIdx.x * blockDim.x + threadIdx.x;
    if (id >= 128 * 64 * 8) return;
    int cg = id >> 9;
    int r  = (id >> 3) & 63;
    int j  = id & 7;
    const float4 f0 = *reinterpret_cast<const float4*>(A + (size_t)r * KDIM + cg * 64 + j * 8);
    const float4 f1 = *reinterpret_cast<const float4*>(A + (size_t)r * KDIM + cg * 64 + j * 8 + 4);
    half2 h[4] = { __floats2half2_rn(f0.x, f0.y), __floats2half2_rn(f0.z, f0.w),
                   __floats2half2_rn(f1.x, f1.y), __floats2half2_rn(f1.z, f1.w) };
    *reinterpret_cast<uint4*>(g_A2 + (size_t)cg * 4096 + r * 64 + ((j ^ (r & 7)) * 8)) =
        *reinterpret_cast<uint4*>(h);
}

__global__ __launch_bounds__(THREADS, 3)
void awq_gemm_kernel(const int*   __restrict__ qw,
                     const float* __restrict__ scales,
                     const float* __restrict__ bias,
                     float*       __restrict__ out)
{
    extern __shared__ char dsm_raw[];
    __shared__ __align__(8) uint64_t m_full[2][STAGES];
    __shared__ __align__(8) uint64_t m_free[2][STAGES];
    __shared__ float red[2048];   // 8 KB dedicated reduction buffer (two passes)

    uint32_t raw = smem_u32(dsm_raw);
    const uint32_t A_smem = (raw + 1023u) & ~1023u;

    const int tid  = threadIdx.x;
    const int lane = tid & 31;
    const int wid  = tid >> 5;
    const int rg   = wid >> 2;          // K-group 0/1
    const int wn   = wid & 3;           // N-warp: cols [wn*16, wn*16+16)
    const int gidq = lane >> 2;         // 0..7
    const int tj   = lane & 3;          // 0..3
    const int n0   = blockIdx.x * NTILE;
    const int cb   = rg * CHALF;        // global chunk base for this K-group

    if (tid == 0) {
        #pragma unroll
        for (int r = 0; r < 2; ++r)
            #pragma unroll
            for (int s = 0; s < STAGES; ++s) {
                mbar_init(smem_u32(&m_full[r][s]), 1);
                mbar_init(smem_u32(&m_free[r][s]), 4);
            }
    }
    __syncthreads();

    const uint32_t ring_base = A_smem + (uint32_t)rg * (STAGES * A_STAGE_BYTES);
    const bool producer = (lane == 0) && (wn == 0);   // warp 0 -> ring0, warp 4 -> ring1

    // Prologue: each producer issues its ring's chunks 0..2
    if (producer) {
        #pragma unroll
        for (int p = 0; p < 3; ++p)
            bulk_ld(ring_base + p * A_STAGE_BYTES, g_A2 + (size_t)(cb + p) * 4096,
                    smem_u32(&m_full[rg][p]));
    }

    // q: per-warp direct LDG. Round r loads word-rows {2r, 2r+1}:
    // lanes 0-15 row 2r, lanes 16-31 row 2r+1; col = lane&15 within warp's 16.
    const int kwofs = lane >> 4;
    const int qcol  = n0 + wn * 16 + (lane & 15);
    uint32_t qc[4], qn[4];
    #pragma unroll
    for (int r = 0; r < 4; ++r)
        qc[r] = __ldg((const uint32_t*)qw + (size_t)(cb * 8 + 2 * r + kwofs) * NDIM + qcol);

    // scales: cols wn*16 + gidq (+8)
    const int scol = n0 + wn * 16 + gidq;
    float sf0 = __ldg(scales + (size_t)(rg * 32) * NDIM + scol);
    float sf1 = __ldg(scales + (size_t)(rg * 32) * NDIM + scol + 8);

    float acc[4][2][4];
    #pragma unroll
    for (int i = 0; i < 4; i++)
        #pragma unroll
        for (int j = 0; j < 2; j++)
            #pragma unroll
            for (int k = 0; k < 4; k++) acc[i][j][k] = 0.f;

    half2 s2[2];
    const half2 C1032 = __half2half2(__ushort_as_half((unsigned short)0x6408)); // 1032.0

    for (int c = 0; c < CHALF; ++c) {
        // Producer: issue chunk c+3 (wait stage free once ring wraps)
        if (producer && c + 3 < CHALF) {
            const int cc = c + 3, st = cc & 3;
            if (cc >= 4) mbar_wait(smem_u32(&m_free[rg][st]), ((cc >> 2) - 1) & 1);
            bulk_ld(ring_base + st * A_STAGE_BYTES, g_A2 + (size_t)(cb + cc) * 4096,
                    smem_u32(&m_full[rg][st]));
        }
        // q prefetch next chunk
        if (c + 1 < CHALF) {
            #pragma unroll
            for (int r = 0; r < 4; ++r)
                qn[r] = __ldg((const uint32_t*)qw +
                              (size_t)((cb + c + 1) * 8 + 2 * r + kwofs) * NDIM + qcol);
        }
        // group scales (128 K = 2 chunks)
        if ((c & 1) == 0) {
            s2[0] = __half2half2(__float2half_rn(sf0));
            s2[1] = __half2half2(__float2half_rn(sf1));
            const int gn = rg * 32 + (c >> 1) + 1;
            if (gn < (rg + 1) * 32) {
                sf0 = __ldg(scales + (size_t)gn * NDIM + scol);
                sf1 = __ldg(scales + (size_t)gn * NDIM + scol + 8);
            }
        }

        // A stage ready?
        const int st = c & 3;
        mbar_wait(smem_u32(&m_full[rg][st]), (c >> 2) & 1);
        const uint32_t abase = ring_base + st * A_STAGE_BYTES;

        #pragma unroll
        for (int s = 0; s < 4; ++s) {
            uint32_t a[4][4];
            #pragma unroll
            for (int mf = 0; mf < 4; ++mf) {
                const int row = mf * 16 + (lane & 15);
                const int j   = (2 * s + (lane >> 4)) ^ (row & 7);
                uint32_t addr = abase + row * 128 + j * 16;
                asm volatile("ldmatrix.sync.aligned.m8n8.x4.shared.b16 {%0,%1,%2,%3}, [%4];\n"
                             : "=r"(a[mf][0]), "=r"(a[mf][1]),
                               "=r"(a[mf][2]), "=r"(a[mf][3])
                             : "r"(addr));
            }
            #pragma unroll
            for (int nb = 0; nb < 2; ++nb) {
                const int src = nb * 8 + gidq;
                uint32_t w0 = __shfl_sync(0xffffffffu, qc[s], src);       // word-row 2s
                uint32_t w1 = __shfl_sync(0xffffffffu, qc[s], src + 16);  // word-row 2s+1
                uint32_t q0 = w0 >> (tj * 8);
                uint32_t q1 = w1 >> (tj * 8);
                uint32_t v0 = (q0 & 0x0000000Fu) | ((q0 & 0x000000F0u) << 12) | 0x64006400u;
                uint32_t v1 = (q1 & 0x0000000Fu) | ((q1 & 0x000000F0u) << 12) | 0x64006400u;
                half2 h0 = __hmul2(__hsub2(reinterpret_cast<half2&>(v0), C1032), s2[nb]);
                half2 h1 = __hmul2(__hsub2(reinterpret_cast<half2&>(v1), C1032), s2[nb]);
                uint32_t b0 = reinterpret_cast<uint32_t&>(h0);
                uint32_t b1 = reinterpret_cast<uint32_t&>(h1);
                #pragma unroll
                for (int mf = 0; mf < 4; ++mf) {
                    asm volatile(
                        "mma.sync.aligned.m16n8k16.row.col.f32.f16.f16.f32 "
                        "{%0,%1,%2,%3}, {%4,%5,%6,%7}, {%8,%9}, {%0,%1,%2,%3};\n"
                        : "+f"(acc[mf][nb][0]), "+f"(acc[mf][nb][1]),
                          "+f"(acc[mf][nb][2]), "+f"(acc[mf][nb][3])
                        : "r"(a[mf][0]), "r"(a[mf][1]), "r"(a[mf][2]), "r"(a[mf][3]),
                          "r"(b0), "r"(b1));
                }
            }
        }
        if (lane == 0) mbar_arrive(smem_u32(&m_free[rg][st]));
        #pragma unroll
        for (int r = 0; r < 4; ++r) qc[r] = qn[r];
    }

    // ---- intra-CTA split-K reduction + store (dedicated static smem) ----
    // Two passes over mf halves: rg1 writes 16 floats/thread, rg0 combines
    // with its own partials, applies reference numerics, stores.
    __syncthreads();   // everyone out of the mainloop

    #pragma unroll
    for (int half = 0; half < 2; ++half) {
        if (rg == 1) {
            float* dst = red + (wn * 32 + lane) * 16;
            #pragma unroll
            for (int mf2 = 0; mf2 < 2; ++mf2)
                #pragma unroll
                for (int nb = 0; nb < 2; ++nb)
                    #pragma unroll
                    for (int k = 0; k < 4; ++k)
                        dst[mf2 * 8 + nb * 4 + k] = acc[half * 2 + mf2][nb][k];
        }
        __syncthreads();
        if (rg == 0) {
            const float* src = red + (wn * 32 + lane) * 16;
            #pragma unroll
            for (int mf2 = 0; mf2 < 2; ++mf2) {
                const int mf = half * 2 + mf2;
                #pragma unroll
                for (int nb = 0; nb < 2; ++nb) {
                    float r0 = acc[mf][nb][0] + src[mf2 * 8 + nb * 4 + 0];
                    float r1 = acc[mf][nb][1] + src[mf2 * 8 + nb * 4 + 1];
                    float r2 = acc[mf][nb][2] + src[mf2 * 8 + nb * 4 + 2];
                    float r3 = acc[mf][nb][3] + src[mf2 * 8 + nb * 4 + 3];
                    const int col  = n0 + wn * 16 + nb * 8 + 2 * tj;
                    const int row0 = mf * 16 + gidq;
                    const float2 bf = *reinterpret_cast<const float2*>(bias + col);
                    half2 hb = __floats2half2_rn(bf.x, bf.y);
                    half2 o0 = __hadd2(__floats2half2_rn(r0, r1), hb);
                    half2 o1 = __hadd2(__floats2half2_rn(r2, r3), hb);
                    *reinterpret_cast<float2*>(out + (size_t)row0 * NDIM + col) =
                        make_float2(__low2float(o0), __high2float(o0));
                    *reinterpret_cast<float2*>(out + (size_t)(row0 + 8) * NDIM + col) =
                        make_float2(__low2float(o1), __high2float(o1));
                }
            }
        }
        __syncthreads();
    }
}

extern "C" void kernel_launch(void* const* d_in, const int* in_sizes, int n_in,
                              void* d_out, int out_size) {
    const float* A      = nullptr;
    const int*   qwt    = nullptr;
    const float* scales = nullptr;
    const float* bias   = nullptr;
    for (int i = 0; i < n_in; ++i) {
        switch (in_sizes[i]) {
            case MDIM * KDIM:        A      = (const float*)d_in[i]; break;
            case (KDIM / 8) * NDIM:  qwt    = (const int*)d_in[i];   break;
            case NGROUPS * NDIM:     scales = (const float*)d_in[i]; break;
            case NDIM:               bias   = (const float*)d_in[i]; break;
            default: break;
        }
    }
    float* out = (float*)d_out;

    cudaFuncSetAttribute(awq_gemm_kernel, cudaFuncAttributeMaxDynamicSharedMemorySize, DSMEM);
    convert_A<<<256, 256>>>(A);
    awq_gemm_kernel<<<NDIM / NTILE, THREADS, DSMEM>>>(qwt, scales, bias, out);  // 448 CTAs
}

// round 13
// speedup vs baseline: 1.6590x; 1.0385x over previous
#include <cuda_runtime.h>
#include <cuda_fp16.h>
#include <cstdint>

// AWQ INT4 dequant GEMM: C[64,28672] = A[64,8192] @ deq(qweight) + bias
// f32 in (harness has no fp16), f32 out. mma.sync m16n8k16.
//
// R13: no smem mainloop at all. Prepass writes A in per-thread FRAGMENT order
// (uint4 per lane per (chunk, s, mf)); mainloop reads them with coalesced
// LDG.128 (L1-cached, 1MB working set). PRMT + vector-constant dequant:
// {1024+nlo, 1024+16*nhi} - {1032,1152} times {s, s/16} -- every step exact
// except the one final mul rounding (bitwise identical to reference fp16
// weights). Intra-CTA split-K 2x4 warps; static-smem reduction epilogue
// (verified R12). Zero syncs/mbarriers in the mainloop.

#define MDIM 64
#define KDIM 8192
#define NDIM 28672
#define NGROUPS 64
#define NTILE 64
#define CHALF 64              // chunks per K-group
#define THREADS 256

__device__ __align__(16) uint4 g_Af[128 * 512];   // 1 MB: [chunk][s*4+mf][lane]

// Prepass: f32 A -> fp16 fragments.
// For (c, s, mf, lane): gidq=lane>>2, tj=lane&3, r0=mf*16+gidq, k0=c*64+s*16+2tj
//   x={A[r0][k0],A[r0][k0+1]}  y={A[r0+8][k0],..}  z={A[r0][k0+8],..}  w={A[r0+8][k0+8],..}
__global__ void convert_A_frag(const float* __restrict__ A)
{
    int t = blockIdx.x * blockDim.x + threadIdx.x;
    if (t >= 128 * 512) return;
    const int c    = t >> 9;
    const int rest = t & 511;
    const int s    = rest >> 7;
    const int mf   = (rest >> 5) & 3;
    const int lane = rest & 31;
    const int gidq = lane >> 2;
    const int tj   = lane & 3;
    const int r0 = mf * 16 + gidq;
    const int k0 = c * 64 + s * 16 + 2 * tj;

    const float2 p0 = *reinterpret_cast<const float2*>(A + (size_t)r0 * KDIM + k0);
    const float2 p1 = *reinterpret_cast<const float2*>(A + (size_t)(r0 + 8) * KDIM + k0);
    const float2 p2 = *reinterpret_cast<const float2*>(A + (size_t)r0 * KDIM + k0 + 8);
    const float2 p3 = *reinterpret_cast<const float2*>(A + (size_t)(r0 + 8) * KDIM + k0 + 8);
    half2 h0 = __floats2half2_rn(p0.x, p0.y);
    half2 h1 = __floats2half2_rn(p1.x, p1.y);
    half2 h2 = __floats2half2_rn(p2.x, p2.y);
    half2 h3 = __floats2half2_rn(p3.x, p3.y);
    uint4 u;
    u.x = reinterpret_cast<uint32_t&>(h0);
    u.y = reinterpret_cast<uint32_t&>(h1);
    u.z = reinterpret_cast<uint32_t&>(h2);
    u.w = reinterpret_cast<uint32_t&>(h3);
    g_Af[t] = u;
}

__global__ __launch_bounds__(THREADS, 3)
void awq_gemm_kernel(const int*   __restrict__ qw,
                     const float* __restrict__ scales,
                     const float* __restrict__ bias,
                     float*       __restrict__ out)
{
    __shared__ float red[2048];   // 8 KB reduction buffer

    const int tid  = threadIdx.x;
    const int lane = tid & 31;
    const int wid  = tid >> 5;
    const int rg   = wid >> 2;          // K-group 0/1
    const int wn   = wid & 3;           // N-warp: cols [wn*16, wn*16+16)
    const int gidq = lane >> 2;         // 0..7
    const int tj   = lane & 3;          // 0..3
    const int n0   = blockIdx.x * NTILE;
    const int cb   = rg * CHALF;        // global chunk base

    const uint32_t selr = (uint32_t)tj * 0x1111u;   // PRMT: byte tj -> all bytes

    // q: round r loads word-rows {2r, 2r+1}: lanes 0-15 row 2r, 16-31 row 2r+1
    const int kwofs = lane >> 4;
    const int qcol  = n0 + wn * 16 + (lane & 15);
    uint32_t qc[4], qn[4];
    #pragma unroll
    for (int r = 0; r < 4; ++r)
        qc[r] = __ldg((const uint32_t*)qw + (size_t)(cb * 8 + 2 * r + kwofs) * NDIM + qcol);

    const int scol = n0 + wn * 16 + gidq;
    float sf0 = __ldg(scales + (size_t)(rg * 32) * NDIM + scol);
    float sf1 = __ldg(scales + (size_t)(rg * 32) * NDIM + scol + 8);

    float acc[4][2][4];
    #pragma unroll
    for (int i = 0; i < 4; i++)
        #pragma unroll
        for (int j = 0; j < 2; j++)
            #pragma unroll
            for (int k = 0; k < 4; k++) acc[i][j][k] = 0.f;

    // dequant constants: {1032, 1152} and per-group vector scale {s, s/16}
    const uint32_t C2 = 0x64806408u;    // half2(1032.0, 1152.0)
    uint32_t sv[2];

    for (int c = 0; c < CHALF; ++c) {
        const int cg = cb + c;
        // q prefetch next chunk
        if (c + 1 < CHALF) {
            #pragma unroll
            for (int r = 0; r < 4; ++r)
                qn[r] = __ldg((const uint32_t*)qw +
                              (size_t)((cg + 1) * 8 + 2 * r + kwofs) * NDIM + qcol);
        }
        // group scales (128 K = 2 chunks): build {s, s/16} vectors (exact)
        if ((c & 1) == 0) {
            uint32_t b0 = (uint32_t)__half_as_ushort(__float2half_rn(sf0));
            uint32_t b1 = (uint32_t)__half_as_ushort(__float2half_rn(sf1));
            sv[0] = b0 | ((b0 - 0x1000u) << 16);
            sv[1] = b1 | ((b1 - 0x1000u) << 16);
            const int gn = rg * 32 + (c >> 1) + 1;
            if (gn < (rg + 1) * 32) {
                sf0 = __ldg(scales + (size_t)gn * NDIM + scol);
                sf1 = __ldg(scales + (size_t)gn * NDIM + scol + 8);
            }
        }

        const uint4* afrag = g_Af + (size_t)cg * 512 + lane;

        #pragma unroll
        for (int s = 0; s < 4; ++s) {
            uint4 a[4];
            #pragma unroll
            for (int mf = 0; mf < 4; ++mf)
                a[mf] = __ldg(afrag + (s * 4 + mf) * 32);

            #pragma unroll
            for (int nb = 0; nb < 2; ++nb) {
                const int src = nb * 8 + gidq;
                uint32_t w0 = __shfl_sync(0xffffffffu, qc[s], src);       // word-row 2s
                uint32_t w1 = __shfl_sync(0xffffffffu, qc[s], src + 16);  // word-row 2s+1
                uint32_t t0, t1;
                asm("prmt.b32 %0, %1, 0, %2;" : "=r"(t0) : "r"(w0), "r"(selr));
                asm("prmt.b32 %0, %1, 0, %2;" : "=r"(t1) : "r"(w1), "r"(selr));
                uint32_t v0 = (t0 & 0x00F0000Fu) | 0x64006400u;  // {1024+nlo, 1024+16*nhi}
                uint32_t v1 = (t1 & 0x00F0000Fu) | 0x64006400u;
                half2 h0 = __hmul2(__hsub2(reinterpret_cast<half2&>(v0),
                                           reinterpret_cast<const half2&>(C2)),
                                   reinterpret_cast<half2&>(sv[nb]));
                half2 h1 = __hmul2(__hsub2(reinterpret_cast<half2&>(v1),
                                           reinterpret_cast<const half2&>(C2)),
                                   reinterpret_cast<half2&>(sv[nb]));
                uint32_t b0 = reinterpret_cast<uint32_t&>(h0);
                uint32_t b1 = reinterpret_cast<uint32_t&>(h1);
                #pragma unroll
                for (int mf = 0; mf < 4; ++mf) {
                    asm volatile(
                        "mma.sync.aligned.m16n8k16.row.col.f32.f16.f16.f32 "
                        "{%0,%1,%2,%3}, {%4,%5,%6,%7}, {%8,%9}, {%0,%1,%2,%3};\n"
                        : "+f"(acc[mf][nb][0]), "+f"(acc[mf][nb][1]),
                          "+f"(acc[mf][nb][2]), "+f"(acc[mf][nb][3])
                        : "r"(a[mf].x), "r"(a[mf].y), "r"(a[mf].z), "r"(a[mf].w),
                          "r"(b0), "r"(b1));
                }
            }
        }
        #pragma unroll
        for (int r = 0; r < 4; ++r) qc[r] = qn[r];
    }

    // ---- intra-CTA split-K reduction + store (verified R12 epilogue) ----
    __syncthreads();
    #pragma unroll
    for (int half = 0; half < 2; ++half) {
        if (rg == 1) {
            float* dst = red + (wn * 32 + lane) * 16;
            #pragma unroll
            for (int mf2 = 0; mf2 < 2; ++mf2)
                #pragma unroll
                for (int nb = 0; nb < 2; ++nb)
                    #pragma unroll
                    for (int k = 0; k < 4; ++k)
                        dst[mf2 * 8 + nb * 4 + k] = acc[half * 2 + mf2][nb][k];
        }
        __syncthreads();
        if (rg == 0) {
            const float* src = red + (wn * 32 + lane) * 16;
            #pragma unroll
            for (int mf2 = 0; mf2 < 2; ++mf2) {
                const int mf = half * 2 + mf2;
                #pragma unroll
                for (int nb = 0; nb < 2; ++nb) {
                    float r0 = acc[mf][nb][0] + src[mf2 * 8 + nb * 4 + 0];
                    float r1 = acc[mf][nb][1] + src[mf2 * 8 + nb * 4 + 1];
                    float r2 = acc[mf][nb][2] + src[mf2 * 8 + nb * 4 + 2];
                    float r3 = acc[mf][nb][3] + src[mf2 * 8 + nb * 4 + 3];
                    const int col  = n0 + wn * 16 + nb * 8 + 2 * tj;
                    const int row0 = mf * 16 + gidq;
                    const float2 bf = *reinterpret_cast<const float2*>(bias + col);
                    half2 hb = __floats2half2_rn(bf.x, bf.y);
                    half2 o0 = __hadd2(__floats2half2_rn(r0, r1), hb);
                    half2 o1 = __hadd2(__floats2half2_rn(r2, r3), hb);
                    *reinterpret_cast<float2*>(out + (size_t)row0 * NDIM + col) =
                        make_float2(__low2float(o0), __high2float(o0));
                    *reinterpret_cast<float2*>(out + (size_t)(row0 + 8) * NDIM + col) =
                        make_float2(__low2float(o1), __high2float(o1));
                }
            }
        }
        __syncthreads();
    }
}

extern "C" void kernel_launch(void* const* d_in, const int* in_sizes, int n_in,
                              void* d_out, int out_size) {
    const float* A      = nullptr;
    const int*   qwt    = nullptr;
    const float* scales = nullptr;
    const float* bias   = nullptr;
    for (int i = 0; i < n_in; ++i) {
        switch (in_sizes[i]) {
            case MDIM * KDIM:        A      = (const float*)d_in[i]; break;
            case (KDIM / 8) * NDIM:  qwt    = (const int*)d_in[i];   break;
            case NGROUPS * NDIM:     scales = (const float*)d_in[i]; break;
            case NDIM:               bias   = (const float*)d_in[i]; break;
            default: break;
        }
    }
    float* out = (float*)d_out;

    convert_A_frag<<<256, 256>>>(A);
    awq_gemm_kernel<<<NDIM / NTILE, THREADS>>>(qwt, scales, bias, out);  // 448 CTAs
}